// round 4
// baseline (speedup 1.0000x reference)
#include <cuda_runtime.h>

#define MULD 32
#define NPB 32          // nodes per block (8 warps x 4 nodes)
#define THREADS 256

// SMEM (dynamic, 72KB):
//   wP: float2[1024] = (w0x, w1b) per (j,k)      8KB  @0
//   wQ: float2[1024] = (w0y, w1a)                8KB  @8KB
//   wR: float2[1024] = (w2a, w2b)                8KB  @16KB
//   Ash: float4[32][32] (s1,v1x,v1y,v1z)        16KB  @24KB
//   Bsh2: 2x float4 [32 nodes][32 j]            32KB  @40KB
//        q0=(s,s,v0,v1)  q1=(v2,v0,v1,v2)
//   xs (prologue) overlays wP/wQ: float[32][128] 16KB

typedef unsigned long long u64;

__device__ __forceinline__ u64 pk(float lo, float hi) {
    u64 r; asm("mov.b64 %0, {%1, %2};" : "=l"(r) : "f"(lo), "f"(hi)); return r;
}
__device__ __forceinline__ void fma2(u64& d, u64 a, u64 b) {
    asm("fma.rn.f32x2 %0, %1, %2, %0;" : "+l"(d) : "l"(a), "l"(b));
}
__device__ __forceinline__ float2 up(u64 v) {
    float2 r; asm("mov.b64 {%0, %1}, %2;" : "=f"(r.x), "=f"(r.y) : "l"(v)); return r;
}

__global__ __launch_bounds__(THREADS, 2)
void td_kernel(const float* __restrict__ x,
               const float* __restrict__ W1_0, const float* __restrict__ W1_1,
               const float* __restrict__ W2_0, const float* __restrict__ W2_1,
               const float* __restrict__ W3_0e, const float* __restrict__ W3_1o,
               const float* __restrict__ W3_1e, const float* __restrict__ W3_2e,
               float* __restrict__ out, int N)
{
    extern __shared__ float smem[];
    float2* wP  = (float2*)smem;                 // [1024]
    float2* wQ  = wP + 1024;
    float2* wR  = wQ + 1024;
    float4* Ash = (float4*)(wR + 1024);          // [1024]
    float4* Bsh = Ash + 1024;                    // [2048] : 2 float4 per (node,j)
    float*  xs  = smem;                          // prologue overlay [32*128]

    const int tid = threadIdx.x;
    const int n0  = blockIdx.x * NPB;

    // ---- stage x rows ----
    for (int e = tid; e < NPB * 128; e += THREADS) {
        int node = e >> 7;
        xs[e] = (n0 + node < N) ? x[(size_t)(n0 + node) * 128 + (e & 127)] : 0.0f;
    }
    __syncthreads();

    // ---- prologue: A=(s@W1_0, v@W1_1), B=(s@W2_0, v@W2_1) ----
    for (int t = tid; t < NPB * 32 * 2; t += THREADS) {
        int which = (t >= NPB * 32);
        int tt = t & (NPB * 32 - 1);
        int node = tt >> 5, i = tt & 31;
        const float* Ws = which ? W2_0 : W1_0;
        const float* Wv = which ? W2_1 : W1_1;
        const float* xr = xs + node * 128;
        float s = 0.f, v0 = 0.f, v1 = 0.f, v2 = 0.f;
        #pragma unroll
        for (int m = 0; m < 32; ++m) {
            float ws = Ws[m * 32 + i];
            float wv = Wv[m * 32 + i];
            s  += xr[m] * ws;
            v0 += xr[32 + 3 * m + 0] * wv;
            v1 += xr[32 + 3 * m + 1] * wv;
            v2 += xr[32 + 3 * m + 2] * wv;
        }
        if (which) {
            Bsh[(node * 32 + i) * 2 + 0] = make_float4(s,  s,  v0, v1);
            Bsh[(node * 32 + i) * 2 + 1] = make_float4(v2, v0, v1, v2);
        } else {
            Ash[node * 32 + i] = make_float4(s, v0, v1, v2);
        }
    }
    __syncthreads();

    const int wid = tid >> 5;
    const int k   = tid & 31;
    const int nb  = wid * 4;    // first of 4 nodes for this warp

    float acc[4][13];
    #pragma unroll
    for (int a = 0; a < 4; ++a)
        #pragma unroll
        for (int q = 0; q < 13; ++q) acc[a][q] = 0.f;

    for (int i = 0; i < 32; ++i) {
        __syncthreads();
        {   // cooperative weight chunk load: 1024 (j,k) cells, 3 float2 each
            int e = tid;
            #pragma unroll
            for (int r = 0; r < 4; ++r, e += THREADS) {
                int g = (i * 32 + (e >> 5)) * 32 + (e & 31);
                float a0 = W3_0e[g],        a1 = W3_0e[32768 + g];
                float b0 = W3_1o[g],        b1 = W3_1o[32768 + g];
                float c0 = W3_1e[g],        c1 = W3_2e[g];
                wP[e] = make_float2(a0, b1);   // (w0x, w1b)
                wQ[e] = make_float2(a1, b0);   // (w0y, w1a)
                wR[e] = make_float2(c0, c1);   // (w2a, w2b)
            }
        }
        __syncthreads();

        u64 M[4][7];
        #pragma unroll
        for (int a = 0; a < 4; ++a)
            #pragma unroll
            for (int q = 0; q < 7; ++q) M[a][q] = 0ull;

        const u64* wPu = (const u64*)wP;
        const u64* wQu = (const u64*)wQ;
        const u64* wRu = (const u64*)wR;

        #pragma unroll 4
        for (int j = 0; j < 32; ++j) {
            const int idx = j * 32 + k;
            u64 Pm0 = wPu[idx];              // (w0x, w1b)
            u64 Pm2 = wQu[idx];              // (w0y, w1a)
            u64 Pm5 = wRu[idx];              // (w2a, w2b)
            float2 qf = up(Pm2);
            float2 rf = up(Pm5);
            u64 Pm1 = pk(qf.x, qf.x);        // (w0y, w0y)
            u64 Pm3 = pk(qf.y, qf.y);        // (w1a, w1a)
            u64 Pm4 = pk(rf.x, rf.x);        // (w2a, w2a)
            u64 Pm6 = pk(rf.y, rf.y);        // (w2b, w2b)

            #pragma unroll
            for (int a = 0; a < 4; ++a) {
                const ulonglong2* bp = (const ulonglong2*)&Bsh[((nb + a) * 32 + j) * 2];
                ulonglong2 e01 = bp[0];      // E0=(s,s)  E1=(v0,v1)
                ulonglong2 e23 = bp[1];      // E2=(v2,v0) E3=(v1,v2)
                fma2(M[a][0], Pm0, e01.x);   // (m0,  m7)
                fma2(M[a][1], Pm1, e01.y);   // (m1,  m2)
                fma2(M[a][2], Pm2, e23.x);   // (m3,  m4)
                fma2(M[a][3], Pm3, e23.y);   // (m5,  m6)
                fma2(M[a][4], Pm4, e01.y);   // (m8,  m9)
                fma2(M[a][5], Pm5, e23.x);   // (m10, m11)
                fma2(M[a][6], Pm6, e23.y);   // (m12, m13)
            }
        }

        // ---- fold with A_i ----
        #pragma unroll
        for (int a = 0; a < 4; ++a) {
            float4 av = Ash[(nb + a) * 32 + i];
            float2 u0 = up(M[a][0]), u1 = up(M[a][1]), u2 = up(M[a][2]),
                   u3 = up(M[a][3]), u4 = up(M[a][4]), u5 = up(M[a][5]),
                   u6 = up(M[a][6]);
            float m0 = u0.x, m7 = u0.y;
            float m1 = u1.x, m2 = u1.y;
            float m3 = u2.x, m4 = u2.y;
            float m5 = u3.x, m6 = u3.y;
            float m8 = u4.x, m9 = u4.y;
            float m10 = u5.x, m11 = u5.y;
            float m12 = u6.x, m13 = u6.y;
            acc[a][0]  += av.x * m0;
            acc[a][1]  += av.y * m1  + av.z * m2  + av.w * m3;
            acc[a][2]  += av.x * m4  + av.y * m7;
            acc[a][3]  += av.x * m5  + av.z * m7;
            acc[a][4]  += av.x * m6  + av.w * m7;
            acc[a][5]  += av.z * m10 - av.w * m9;
            acc[a][6]  += av.w * m8  - av.y * m10;
            acc[a][7]  += av.y * m9  - av.z * m8;
            acc[a][8]  += av.y * m13 + av.w * m11;
            acc[a][9]  += av.y * m12 + av.z * m11;
            acc[a][10] += 2.f * av.z * m12 - av.y * m11 - av.w * m13;
            acc[a][11] += av.z * m13 + av.w * m12;
            acc[a][12] += av.w * m13 - av.y * m11;
        }
    }

    // ---- outputs ----
    const float C0  = -0.57735026918962576f;
    const float C1  = -0.70710678118654752f;
    const float C2  =  0.70710678118654752f;
    const float C2z =  0.40824829046386302f;

    #pragma unroll
    for (int a = 0; a < 4; ++a) {
        int node = n0 + nb + a;
        if (node >= N) continue;
        float* o = out + (size_t)node * 384;
        const float* c = acc[a];
        o[k] = c[0] + C0 * c[1];
        o[32  + 3 * k + 0] = c[2];
        o[32  + 3 * k + 1] = c[3];
        o[32  + 3 * k + 2] = c[4];
        o[128 + 3 * k + 0] = C1 * c[5];
        o[128 + 3 * k + 1] = C1 * c[6];
        o[128 + 3 * k + 2] = C1 * c[7];
        o[224 + 5 * k + 0] = C2 * c[8];
        o[224 + 5 * k + 1] = C2 * c[9];
        o[224 + 5 * k + 2] = C2z * c[10];
        o[224 + 5 * k + 3] = C2 * c[11];
        o[224 + 5 * k + 4] = C2 * c[12];
    }
}

extern "C" void kernel_launch(void* const* d_in, const int* in_sizes, int n_in,
                              void* d_out, int out_size)
{
    const float* x     = (const float*)d_in[0];
    const float* W1_0  = (const float*)d_in[1];
    const float* W1_1  = (const float*)d_in[2];
    const float* W2_0  = (const float*)d_in[3];
    const float* W2_1  = (const float*)d_in[4];
    const float* W3_0e = (const float*)d_in[5];
    const float* W3_1o = (const float*)d_in[6];
    const float* W3_1e = (const float*)d_in[7];
    const float* W3_2e = (const float*)d_in[8];

    int N = in_sizes[0] / (4 * MULD);
    int blocks = (N + NPB - 1) / NPB;
    size_t smem = 3 * 1024 * sizeof(float2)        // weights 24KB
                + 1024 * sizeof(float4)            // Ash 16KB
                + 2048 * sizeof(float4);           // Bsh 32KB  => 72KB

    // Unconditional, idempotent, graph-capture-legal. No static guards
    // (harness contract: kernel_launch must do identical work every call).
    cudaFuncSetAttribute(td_kernel, cudaFuncAttributeMaxDynamicSharedMemorySize,
                         (int)smem);

    td_kernel<<<blocks, THREADS, smem>>>(x, W1_0, W1_1, W2_0, W2_1,
                                         W3_0e, W3_1o, W3_1e, W3_2e,
                                         (float*)d_out, N);
}

// round 5
// speedup vs baseline: 1.0495x; 1.0495x over previous
#include <cuda_runtime.h>

#define MULD 32
#define NPB 16          // nodes per block (8 warps x 2 nodes)
#define THREADS 256

// SMEM (dynamic, 64KB), double-buffered weights:
//   wABbuf: float4[2][1024] = (w0x, w0y, w1y, w1x) per (j,k)  32KB  @0
//   wCbuf : float2[2][1024] = (w2x, w2y)                      16KB  @32KB
//   Ash: float4[16][32] (s1, v1x, v1y, v1z)                    8KB  @48KB
//   Bsh: float4[16][32] (s2, v2x, v2y, v2z)                    8KB  @56KB
//   xs (prologue only) overlays wABbuf: float[16][128]          8KB

typedef unsigned long long u64;

__device__ __forceinline__ u64 pk(float lo, float hi) {
    u64 r; asm("mov.b64 %0, {%1, %2};" : "=l"(r) : "f"(lo), "f"(hi)); return r;
}
__device__ __forceinline__ void fma2(u64& d, u64 a, u64 b) {
    asm("fma.rn.f32x2 %0, %1, %2, %0;" : "+l"(d) : "l"(a), "l"(b));
}
__device__ __forceinline__ float2 up(u64 v) {
    float2 r; asm("mov.b64 {%0, %1}, %2;" : "=f"(r.x), "=f"(r.y) : "l"(v)); return r;
}

__global__ __launch_bounds__(THREADS, 3)
void td_kernel(const float* __restrict__ x,
               const float* __restrict__ W1_0, const float* __restrict__ W1_1,
               const float* __restrict__ W2_0, const float* __restrict__ W2_1,
               const float* __restrict__ W3_0e, const float* __restrict__ W3_1o,
               const float* __restrict__ W3_1e, const float* __restrict__ W3_2e,
               float* __restrict__ out, int N)
{
    extern __shared__ float smem[];
    float4* wABbuf = (float4*)smem;             // [2][1024]
    float2* wCbuf  = (float2*)(wABbuf + 2048);  // [2][1024]
    float4* Ash    = (float4*)(wCbuf + 2048);   // [512]
    float4* Bsh    = Ash + NPB * 32;            // [512]
    float*  xs     = smem;                      // prologue overlay

    const int tid = threadIdx.x;
    const int n0  = blockIdx.x * NPB;

    // ---- stage x rows ----
    for (int e = tid; e < NPB * 128; e += THREADS) {
        int node = e >> 7;
        xs[e] = (n0 + node < N) ? x[(size_t)(n0 + node) * 128 + (e & 127)] : 0.0f;
    }
    __syncthreads();

    // ---- prologue: A=(s@W1_0, v@W1_1), B=(s@W2_0, v@W2_1) ----
    for (int t = tid; t < NPB * 32 * 2; t += THREADS) {
        int which = (t >= NPB * 32);
        int tt = t & (NPB * 32 - 1);
        int node = tt >> 5, i = tt & 31;
        const float* Ws = which ? W2_0 : W1_0;
        const float* Wv = which ? W2_1 : W1_1;
        const float* xr = xs + node * 128;
        float s = 0.f, v0 = 0.f, v1 = 0.f, v2 = 0.f;
        #pragma unroll
        for (int m = 0; m < 32; ++m) {
            float ws = Ws[m * 32 + i];
            float wv = Wv[m * 32 + i];
            s  += xr[m] * ws;
            v0 += xr[32 + 3 * m + 0] * wv;
            v1 += xr[32 + 3 * m + 1] * wv;
            v2 += xr[32 + 3 * m + 2] * wv;
        }
        float4 r = make_float4(s, v0, v1, v2);
        if (which) Bsh[node * 32 + i] = r;
        else       Ash[node * 32 + i] = r;
    }
    __syncthreads();   // also guards xs overlay before chunk-0 staging

    // ---- stage weight chunk 0 into buffer 0 ----
    {
        int e = tid;
        #pragma unroll
        for (int r = 0; r < 4; ++r, e += THREADS) {
            int g = (e >> 5) * 32 + (e & 31);   // i = 0
            wABbuf[e] = make_float4(W3_0e[g], W3_0e[32768 + g],
                                    W3_1o[32768 + g], W3_1o[g]);
            wCbuf[e]  = make_float2(W3_1e[g], W3_2e[g]);
        }
    }
    __syncthreads();

    const int wid = tid >> 5;
    const int k   = tid & 31;
    const int nA  = wid * 2;
    const int nB  = wid * 2 + 1;

    float acc[2][13];
    #pragma unroll
    for (int a = 0; a < 2; ++a)
        #pragma unroll
        for (int q = 0; q < 13; ++q) acc[a][q] = 0.f;

    for (int i = 0; i < 32; ++i) {
        const float4* wAB = wABbuf + (i & 1) * 1024;
        const float2* wC  = wCbuf  + (i & 1) * 1024;

        // ---- stage chunk i+1 into the other buffer (overlaps compute) ----
        if (i < 31) {
            float4* wABn = wABbuf + ((i + 1) & 1) * 1024;
            float2* wCn  = wCbuf  + ((i + 1) & 1) * 1024;
            int e = tid;
            #pragma unroll
            for (int r = 0; r < 4; ++r, e += THREADS) {
                int g = ((i + 1) * 32 + (e >> 5)) * 32 + (e & 31);
                wABn[e] = make_float4(W3_0e[g], W3_0e[32768 + g],
                                      W3_1o[32768 + g], W3_1o[g]);
                wCn[e]  = make_float2(W3_1e[g], W3_2e[g]);
            }
        }

        // ---- moments over j ----
        u64 MA0=0, MA1=0, MA2=0, MA3=0, MA4=0, MA5=0;
        u64 MB0=0, MB1=0, MB2=0, MB3=0, MB4=0, MB5=0;
        float mA8 = 0.f, mA11 = 0.f, mB8 = 0.f, mB11 = 0.f;

        const float4* BA = Bsh + nA * 32;
        const float4* BB = Bsh + nB * 32;

        #pragma unroll 8
        for (int j = 0; j < 32; ++j) {
            const int idx = j * 32 + k;
            ulonglong2 w01 = *(const ulonglong2*)&wAB[idx]; // (w0x,w0y),(w1y,w1x)
            float2 cf = wC[idx];                            // (w2x, w2y)
            float2 p1f = up(w01.x);
            float2 p3f = up(w01.y);
            u64 P2  = pk(p1f.y, p1f.y);   // (w0y, w0y)
            u64 P4  = pk(p3f.y, p3f.y);   // (w1x, w1x)
            u64 S2x = pk(cf.x, cf.x);
            u64 S2y = pk(cf.y, cf.y);

            ulonglong2 ba = *(const ulonglong2*)&BA[j];     // (bx,by),(bz,bw)
            fma2(MA0, w01.x, ba.x);
            fma2(MA1, P2,    ba.y);
            fma2(MA2, w01.y, ba.x);
            fma2(MA3, P4,    ba.y);
            fma2(MA4, S2x,   ba.y);
            fma2(MA5, S2y,   ba.y);
            float2 baxy = up(ba.x);
            mA8  += cf.x * baxy.y;
            mA11 += cf.y * baxy.y;

            ulonglong2 bb = *(const ulonglong2*)&BB[j];
            fma2(MB0, w01.x, bb.x);
            fma2(MB1, P2,    bb.y);
            fma2(MB2, w01.y, bb.x);
            fma2(MB3, P4,    bb.y);
            fma2(MB4, S2x,   bb.y);
            fma2(MB5, S2y,   bb.y);
            float2 bbxy = up(bb.x);
            mB8  += cf.x * bbxy.y;
            mB11 += cf.y * bbxy.y;
        }

        // ---- fold with A_i ----
        {
            float4 a0 = Ash[nA * 32 + i];
            float2 u0 = up(MA0), u1 = up(MA1), u2 = up(MA2),
                   u3 = up(MA3), u4 = up(MA4), u5 = up(MA5);
            float m0 = u0.x, m1 = u0.y, m2 = u1.x, m3 = u1.y;
            float m7 = u2.x, m4 = u2.y, m5 = u3.x, m6 = u3.y;
            float m9 = u4.x, m10 = u4.y, m12 = u5.x, m13 = u5.y;
            float m8 = mA8, m11 = mA11;
            acc[0][0]  += a0.x * m0;
            acc[0][1]  += a0.y * m1  + a0.z * m2  + a0.w * m3;
            acc[0][2]  += a0.x * m4  + a0.y * m7;
            acc[0][3]  += a0.x * m5  + a0.z * m7;
            acc[0][4]  += a0.x * m6  + a0.w * m7;
            acc[0][5]  += a0.z * m10 - a0.w * m9;
            acc[0][6]  += a0.w * m8  - a0.y * m10;
            acc[0][7]  += a0.y * m9  - a0.z * m8;
            acc[0][8]  += a0.y * m13 + a0.w * m11;
            acc[0][9]  += a0.y * m12 + a0.z * m11;
            acc[0][10] += 2.f * a0.z * m12 - a0.y * m11 - a0.w * m13;
            acc[0][11] += a0.z * m13 + a0.w * m12;
            acc[0][12] += a0.w * m13 - a0.y * m11;
        }
        {
            float4 a1 = Ash[nB * 32 + i];
            float2 u0 = up(MB0), u1 = up(MB1), u2 = up(MB2),
                   u3 = up(MB3), u4 = up(MB4), u5 = up(MB5);
            float m0 = u0.x, m1 = u0.y, m2 = u1.x, m3 = u1.y;
            float m7 = u2.x, m4 = u2.y, m5 = u3.x, m6 = u3.y;
            float m9 = u4.x, m10 = u4.y, m12 = u5.x, m13 = u5.y;
            float m8 = mB8, m11 = mB11;
            acc[1][0]  += a1.x * m0;
            acc[1][1]  += a1.y * m1  + a1.z * m2  + a1.w * m3;
            acc[1][2]  += a1.x * m4  + a1.y * m7;
            acc[1][3]  += a1.x * m5  + a1.z * m7;
            acc[1][4]  += a1.x * m6  + a1.w * m7;
            acc[1][5]  += a1.z * m10 - a1.w * m9;
            acc[1][6]  += a1.w * m8  - a1.y * m10;
            acc[1][7]  += a1.y * m9  - a1.z * m8;
            acc[1][8]  += a1.y * m13 + a1.w * m11;
            acc[1][9]  += a1.y * m12 + a1.z * m11;
            acc[1][10] += 2.f * a1.z * m12 - a1.y * m11 - a1.w * m13;
            acc[1][11] += a1.z * m13 + a1.w * m12;
            acc[1][12] += a1.w * m13 - a1.y * m11;
        }

        __syncthreads();   // single barrier: chunk i+1 staged, chunk i consumed
    }

    // ---- outputs ----
    const float C0  = -0.57735026918962576f;
    const float C1  = -0.70710678118654752f;
    const float C2  =  0.70710678118654752f;
    const float C2z =  0.40824829046386302f;

    #pragma unroll
    for (int a = 0; a < 2; ++a) {
        int node = n0 + nA + a;
        if (node >= N) continue;
        float* o = out + (size_t)node * 384;
        const float* c = acc[a];
        o[k] = c[0] + C0 * c[1];
        o[32  + 3 * k + 0] = c[2];
        o[32  + 3 * k + 1] = c[3];
        o[32  + 3 * k + 2] = c[4];
        o[128 + 3 * k + 0] = C1 * c[5];
        o[128 + 3 * k + 1] = C1 * c[6];
        o[128 + 3 * k + 2] = C1 * c[7];
        o[224 + 5 * k + 0] = C2 * c[8];
        o[224 + 5 * k + 1] = C2 * c[9];
        o[224 + 5 * k + 2] = C2z * c[10];
        o[224 + 5 * k + 3] = C2 * c[11];
        o[224 + 5 * k + 4] = C2 * c[12];
    }
}

extern "C" void kernel_launch(void* const* d_in, const int* in_sizes, int n_in,
                              void* d_out, int out_size)
{
    const float* x     = (const float*)d_in[0];
    const float* W1_0  = (const float*)d_in[1];
    const float* W1_1  = (const float*)d_in[2];
    const float* W2_0  = (const float*)d_in[3];
    const float* W2_1  = (const float*)d_in[4];
    const float* W3_0e = (const float*)d_in[5];
    const float* W3_1o = (const float*)d_in[6];
    const float* W3_1e = (const float*)d_in[7];
    const float* W3_2e = (const float*)d_in[8];

    int N = in_sizes[0] / (4 * MULD);
    int blocks = (N + NPB - 1) / NPB;
    size_t smem = 2048 * sizeof(float4)            // wABbuf 32KB
                + 2048 * sizeof(float2)            // wCbuf  16KB
                + 2 * NPB * 32 * sizeof(float4);   // Ash+Bsh 16KB => 64KB

    // Unconditional, idempotent, graph-capture-legal (no static guards).
    cudaFuncSetAttribute(td_kernel, cudaFuncAttributeMaxDynamicSharedMemorySize,
                         (int)smem);

    td_kernel<<<blocks, THREADS, smem>>>(x, W1_0, W1_1, W2_0, W2_1,
                                         W3_0e, W3_1o, W3_1e, W3_2e,
                                         (float*)d_out, N);
}

// round 7
// speedup vs baseline: 1.1351x; 1.0815x over previous
#include <cuda_runtime.h>

#define MULD 32
#define NPB 16          // nodes per block (8 warps x 2 nodes)
#define THREADS 256

// Packed weight streams (filled by pack_kernel on every launch; __device__
// globals are the sanctioned scratch mechanism — no allocation).
//   g_Wab[(i*32+j)*32+k] = (w0x, w0y, w1y, w1x)
//   g_Wc [(i*32+j)*32+k] = (w2x, w2y)
__device__ float4 g_Wab[32768];
__device__ float2 g_Wc[32768];

typedef unsigned long long u64;

__device__ __forceinline__ u64 pk(float lo, float hi) {
    u64 r; asm("mov.b64 %0, {%1, %2};" : "=l"(r) : "f"(lo), "f"(hi)); return r;
}
__device__ __forceinline__ void fma2(u64& d, u64 a, u64 b) {
    asm("fma.rn.f32x2 %0, %1, %2, %0;" : "+l"(d) : "l"(a), "l"(b));
}
__device__ __forceinline__ float2 up(u64 v) {
    float2 r; asm("mov.b64 {%0, %1}, %2;" : "=f"(r.x), "=f"(r.y) : "l"(v)); return r;
}
__device__ __forceinline__ unsigned s2u(const void* p) {
    return (unsigned)__cvta_generic_to_shared(p);
}
__device__ __forceinline__ void cp16(unsigned dst, const void* src) {
    asm volatile("cp.async.cg.shared.global [%0], [%1], 16;" :: "r"(dst), "l"(src));
}
__device__ __forceinline__ void cp8(unsigned dst, const void* src) {
    asm volatile("cp.async.ca.shared.global [%0], [%1], 8;" :: "r"(dst), "l"(src));
}
__device__ __forceinline__ void cp_commit() {
    asm volatile("cp.async.commit_group;" ::: "memory");
}
__device__ __forceinline__ void cp_wait1() {
    asm volatile("cp.async.wait_group 1;" ::: "memory");
}

__global__ void pack_kernel(const float* __restrict__ W3_0e,
                            const float* __restrict__ W3_1o,
                            const float* __restrict__ W3_1e,
                            const float* __restrict__ W3_2e)
{
    int t = blockIdx.x * blockDim.x + threadIdx.x;
    if (t < 32768) {
        g_Wab[t] = make_float4(W3_0e[t], W3_0e[32768 + t],
                               W3_1o[32768 + t], W3_1o[t]);
        g_Wc[t]  = make_float2(W3_1e[t], W3_2e[t]);
    }
}

// SMEM (dynamic, 64KB), double-buffered weights:
//   wABbuf: float4[2][1024]  32KB  @0
//   wCbuf : float2[2][1024]  16KB  @32KB
//   Ash: float4[16][32]       8KB  @48KB
//   Bsh: float4[16][32]       8KB  @56KB   (layout: s, v0, v1, v2)
//   xs (prologue) overlays wABbuf[0]: float[16][128] 8KB

__global__ __launch_bounds__(THREADS, 3)
void td_kernel(const float* __restrict__ x,
               const float* __restrict__ W1_0, const float* __restrict__ W1_1,
               const float* __restrict__ W2_0, const float* __restrict__ W2_1,
               float* __restrict__ out, int N)
{
    extern __shared__ float smem[];
    float4* wABbuf = (float4*)smem;             // [2][1024]
    float2* wCbuf  = (float2*)(wABbuf + 2048);  // [2][1024]
    float4* Ash    = (float4*)(wCbuf + 2048);   // [512]
    float4* Bsh    = Ash + NPB * 32;            // [512]
    float*  xs     = smem;                      // prologue overlay

    const int tid = threadIdx.x;
    const int n0  = blockIdx.x * NPB;

    // ---- stage x rows ----
    for (int e = tid; e < NPB * 128; e += THREADS) {
        int node = e >> 7;
        xs[e] = (n0 + node < N) ? x[(size_t)(n0 + node) * 128 + (e & 127)] : 0.0f;
    }
    __syncthreads();

    // ---- prologue: A=(s@W1_0, v@W1_1), B=(s@W2_0, v@W2_1) ----
    for (int t = tid; t < NPB * 32 * 2; t += THREADS) {
        int which = (t >= NPB * 32);
        int tt = t & (NPB * 32 - 1);
        int node = tt >> 5, i = tt & 31;
        const float* Ws = which ? W2_0 : W1_0;
        const float* Wv = which ? W2_1 : W1_1;
        const float* xr = xs + node * 128;
        float s = 0.f, v0 = 0.f, v1 = 0.f, v2 = 0.f;
        #pragma unroll
        for (int m = 0; m < 32; ++m) {
            float ws = Ws[m * 32 + i];
            float wv = Wv[m * 32 + i];
            s  += xr[m] * ws;
            v0 += xr[32 + 3 * m + 0] * wv;
            v1 += xr[32 + 3 * m + 1] * wv;
            v2 += xr[32 + 3 * m + 2] * wv;
        }
        float4 r = make_float4(s, v0, v1, v2);
        if (which) Bsh[node * 32 + i] = r;
        else       Ash[node * 32 + i] = r;
    }
    __syncthreads();   // xs overlay fully consumed

    // ---- async-stage chunks 0 and 1 ----
    const unsigned sAB = s2u(wABbuf);
    const unsigned sC  = s2u(wCbuf);
    {
        #pragma unroll
        for (int r = 0; r < 4; ++r) {
            int e = tid + r * THREADS;
            cp16(sAB + e * 16, g_Wab + e);
            cp8 (sC  + e * 8,  g_Wc  + e);
        }
        cp_commit();
        #pragma unroll
        for (int r = 0; r < 4; ++r) {
            int e = tid + r * THREADS;
            cp16(sAB + 16384 + e * 16, g_Wab + 1024 + e);
            cp8 (sC  + 8192  + e * 8,  g_Wc  + 1024 + e);
        }
        cp_commit();
    }

    const int wid = tid >> 5;
    const int k   = tid & 31;
    const int nA  = wid * 2;
    const int nB  = wid * 2 + 1;

    float acc[2][13];
    #pragma unroll
    for (int a = 0; a < 2; ++a)
        #pragma unroll
        for (int q = 0; q < 13; ++q) acc[a][q] = 0.f;

    for (int i = 0; i < 32; ++i) {
        // Pending groups here: {G_i, G_{i+1}} (tail: {G31, E30}); wait_group 1
        // retires all but the most recent => chunk i is complete.
        cp_wait1();
        __syncthreads();

        const float4* wAB = wABbuf + (i & 1) * 1024;
        const u64*    wCu = (const u64*)(wCbuf + (i & 1) * 1024);

        u64 MA0=0, MA1=0, MA2=0, MA3=0, MA4=0, MA5=0, MA6=0;
        u64 MB0=0, MB1=0, MB2=0, MB3=0, MB4=0, MB5=0, MB6=0;

        const float4* BA = Bsh + nA * 32;
        const float4* BB = Bsh + nB * 32;

        #pragma unroll 8
        for (int j = 0; j < 32; ++j) {
            const int idx = j * 32 + k;
            ulonglong2 w01 = *(const ulonglong2*)&wAB[idx]; // (w0x,w0y),(w1y,w1x)
            u64 cfu = wCu[idx];                             // (w2x, w2y)
            float2 p1f = up(w01.x);
            float2 p3f = up(w01.y);
            float2 rf  = up(cfu);
            u64 P2  = pk(p1f.y, p1f.y);   // (w0y, w0y)
            u64 P4  = pk(p3f.y, p3f.y);   // (w1x, w1x)
            u64 S2x = pk(rf.x, rf.x);     // (w2x, w2x)
            u64 S2y = pk(rf.y, rf.y);     // (w2y, w2y)

            ulonglong2 ba = *(const ulonglong2*)&BA[j];     // (s,v0),(v1,v2)
            float2 baxy = up(ba.x);
            u64 Dav0 = pk(baxy.y, baxy.y);                  // (v0, v0)
            fma2(MA0, w01.x, ba.x);   // (m0,  m1)
            fma2(MA1, P2,    ba.y);   // (m2,  m3)
            fma2(MA2, w01.y, ba.x);   // (m7,  m4)
            fma2(MA3, P4,    ba.y);   // (m5,  m6)
            fma2(MA4, S2x,   ba.y);   // (m9,  m10)
            fma2(MA5, S2y,   ba.y);   // (m12, m13)
            fma2(MA6, cfu,   Dav0);   // (m8,  m11)

            ulonglong2 bb = *(const ulonglong2*)&BB[j];
            float2 bbxy = up(bb.x);
            u64 Dbv0 = pk(bbxy.y, bbxy.y);
            fma2(MB0, w01.x, bb.x);
            fma2(MB1, P2,    bb.y);
            fma2(MB2, w01.y, bb.x);
            fma2(MB3, P4,    bb.y);
            fma2(MB4, S2x,   bb.y);
            fma2(MB5, S2y,   bb.y);
            fma2(MB6, cfu,   Dbv0);
        }

        // ---- fold with A_i ----
        {
            float4 a0 = Ash[nA * 32 + i];
            float2 u0 = up(MA0), u1 = up(MA1), u2 = up(MA2),
                   u3 = up(MA3), u4 = up(MA4), u5 = up(MA5), u6 = up(MA6);
            float m0 = u0.x, m1 = u0.y, m2 = u1.x, m3 = u1.y;
            float m7 = u2.x, m4 = u2.y, m5 = u3.x, m6 = u3.y;
            float m9 = u4.x, m10 = u4.y, m12 = u5.x, m13 = u5.y;
            float m8 = u6.x, m11 = u6.y;
            acc[0][0]  += a0.x * m0;
            acc[0][1]  += a0.y * m1  + a0.z * m2  + a0.w * m3;
            acc[0][2]  += a0.x * m4  + a0.y * m7;
            acc[0][3]  += a0.x * m5  + a0.z * m7;
            acc[0][4]  += a0.x * m6  + a0.w * m7;
            acc[0][5]  += a0.z * m10 - a0.w * m9;
            acc[0][6]  += a0.w * m8  - a0.y * m10;
            acc[0][7]  += a0.y * m9  - a0.z * m8;
            acc[0][8]  += a0.y * m13 + a0.w * m11;
            acc[0][9]  += a0.y * m12 + a0.z * m11;
            acc[0][10] += 2.f * a0.z * m12 - a0.y * m11 - a0.w * m13;
            acc[0][11] += a0.z * m13 + a0.w * m12;
            acc[0][12] += a0.w * m13 - a0.y * m11;
        }
        {
            float4 a1 = Ash[nB * 32 + i];
            float2 u0 = up(MB0), u1 = up(MB1), u2 = up(MB2),
                   u3 = up(MB3), u4 = up(MB4), u5 = up(MB5), u6 = up(MB6);
            float m0 = u0.x, m1 = u0.y, m2 = u1.x, m3 = u1.y;
            float m7 = u2.x, m4 = u2.y, m5 = u3.x, m6 = u3.y;
            float m9 = u4.x, m10 = u4.y, m12 = u5.x, m13 = u5.y;
            float m8 = u6.x, m11 = u6.y;
            acc[1][0]  += a1.x * m0;
            acc[1][1]  += a1.y * m1  + a1.z * m2  + a1.w * m3;
            acc[1][2]  += a1.x * m4  + a1.y * m7;
            acc[1][3]  += a1.x * m5  + a1.z * m7;
            acc[1][4]  += a1.x * m6  + a1.w * m7;
            acc[1][5]  += a1.z * m10 - a1.w * m9;
            acc[1][6]  += a1.w * m8  - a1.y * m10;
            acc[1][7]  += a1.y * m9  - a1.z * m8;
            acc[1][8]  += a1.y * m13 + a1.w * m11;
            acc[1][9]  += a1.y * m12 + a1.z * m11;
            acc[1][10] += 2.f * a1.z * m12 - a1.y * m11 - a1.w * m13;
            acc[1][11] += a1.z * m13 + a1.w * m12;
            acc[1][12] += a1.w * m13 - a1.y * m11;
        }

        __syncthreads();   // all warps done with buffer (i&1)

        // ---- async-stage chunk i+2 into buffer (i&1) ----
        if (i + 2 < 32) {
            unsigned bAB = sAB + (i & 1) * 16384;
            unsigned bC  = sC  + (i & 1) * 8192;
            int goff = (i + 2) * 1024;
            #pragma unroll
            for (int r = 0; r < 4; ++r) {
                int e = tid + r * THREADS;
                cp16(bAB + e * 16, g_Wab + goff + e);
                cp8 (bC  + e * 8,  g_Wc  + goff + e);
            }
        }
        cp_commit();   // commit every iter (possibly empty): fixed group count
    }

    // ---- outputs ----
    const float C0  = -0.57735026918962576f;
    const float C1  = -0.70710678118654752f;
    const float C2  =  0.70710678118654752f;
    const float C2z =  0.40824829046386302f;

    #pragma unroll
    for (int a = 0; a < 2; ++a) {
        int node = n0 + nA + a;
        if (node >= N) continue;
        float* o = out + (size_t)node * 384;
        const float* c = acc[a];
        o[k] = c[0] + C0 * c[1];
        o[32  + 3 * k + 0] = c[2];
        o[32  + 3 * k + 1] = c[3];
        o[32  + 3 * k + 2] = c[4];
        o[128 + 3 * k + 0] = C1 * c[5];
        o[128 + 3 * k + 1] = C1 * c[6];
        o[128 + 3 * k + 2] = C1 * c[7];
        o[224 + 5 * k + 0] = C2 * c[8];
        o[224 + 5 * k + 1] = C2 * c[9];
        o[224 + 5 * k + 2] = C2z * c[10];
        o[224 + 5 * k + 3] = C2 * c[11];
        o[224 + 5 * k + 4] = C2 * c[12];
    }
}

extern "C" void kernel_launch(void* const* d_in, const int* in_sizes, int n_in,
                              void* d_out, int out_size)
{
    const float* x     = (const float*)d_in[0];
    const float* W1_0  = (const float*)d_in[1];
    const float* W1_1  = (const float*)d_in[2];
    const float* W2_0  = (const float*)d_in[3];
    const float* W2_1  = (const float*)d_in[4];
    const float* W3_0e = (const float*)d_in[5];
    const float* W3_1o = (const float*)d_in[6];
    const float* W3_1e = (const float*)d_in[7];
    const float* W3_2e = (const float*)d_in[8];

    int N = in_sizes[0] / (4 * MULD);
    int blocks = (N + NPB - 1) / NPB;
    size_t smem = 2048 * sizeof(float4)            // wABbuf 32KB
                + 2048 * sizeof(float2)            // wCbuf  16KB
                + 2 * NPB * 32 * sizeof(float4);   // Ash+Bsh 16KB => 64KB

    // Unconditional, idempotent, graph-capture-legal (no static guards).
    cudaFuncSetAttribute(td_kernel, cudaFuncAttributeMaxDynamicSharedMemorySize,
                         (int)smem);

    pack_kernel<<<128, 256>>>(W3_0e, W3_1o, W3_1e, W3_2e);
    td_kernel<<<blocks, THREADS, smem>>>(x, W1_0, W1_1, W2_0, W2_1,
                                         (float*)d_out, N);
}